// round 1
// baseline (speedup 1.0000x reference)
#include <cuda_runtime.h>
#include <math.h>

// Problem constants
#define T    2048
#define HD   1024
#define ID   512
#define NE   32

// ---------------- scratch (device globals: allocation-free) ----------------
__device__ int   g_cnt[NE];
__device__ int   g_tok[NE * T];
__device__ float g_wt [NE * T];
__device__ float g_inter   [(size_t)NE * T * ID];   // routed gate*up activations per slot
__device__ float g_inter_sh[(size_t)T * HD];        // shared-expert intermediate

// ---------------- zero counters ----------------
__global__ void zero_kernel() {
    if (threadIdx.x < NE) g_cnt[threadIdx.x] = 0;
}

// ---------------- router: 1 warp per token ----------------
__global__ void router_kernel(const float* __restrict__ h,
                              const float* __restrict__ gw,
                              const float* __restrict__ gb) {
    __shared__ float s_sc[4][32];
    __shared__ float s_ss[4][32];
    int wid  = threadIdx.x >> 5;
    int lane = threadIdx.x & 31;
    int t = blockIdx.x * 4 + wid;
    if (t >= T) return;

    const float4* hv = (const float4*)(h + (size_t)t * HD);
    const float4* wv = (const float4*)(gw + (size_t)lane * HD);
    float acc = 0.f;
#pragma unroll 8
    for (int j = 0; j < HD / 4; j++) {
        float4 a = hv[j]; float4 b = wv[j];
        acc += a.x * b.x + a.y * b.y + a.z * b.z + a.w * b.w;
    }
    float score = 1.f / (1.f + expf(-acc));
    s_ss[wid][lane] = score;
    s_sc[wid][lane] = score + gb[lane];
    __syncwarp();

    if (lane == 0) {
        float* SC = s_sc[wid];
        float* SS = s_ss[wid];
        // group score = sum of top-2 within each group of 4
        float gs[8];
#pragma unroll
        for (int g = 0; g < 8; g++) {
            float m1 = -1e30f, m2 = -1e30f;
#pragma unroll
            for (int q = 0; q < 4; q++) {
                float v = SC[g * 4 + q];
                if (v > m1) { m2 = m1; m1 = v; }
                else if (v > m2) m2 = v;
            }
            gs[g] = m1 + m2;
        }
        // top-4 groups (strict >: first index wins ties, matches lax.top_k)
        unsigned gsel = 0;
        for (int it = 0; it < 4; it++) {
            float best = -1e30f; int bi = 0;
            for (int g = 0; g < 8; g++)
                if (!((gsel >> g) & 1) && gs[g] > best) { best = gs[g]; bi = g; }
            gsel |= 1u << bi;
        }
        float masked[32];
#pragma unroll
        for (int e = 0; e < 32; e++)
            masked[e] = ((gsel >> (e >> 2)) & 1) ? SC[e] : 0.f;
        // top-8 experts over masked scores
        int tki[8]; float tw[8];
        unsigned used = 0;
        for (int k = 0; k < 8; k++) {
            float best = -1e30f; int bi = 0;
            for (int e = 0; e < 32; e++)
                if (!((used >> e) & 1) && masked[e] > best) { best = masked[e]; bi = e; }
            used |= 1u << bi;
            tki[k] = bi;
            tw[k] = SS[bi];      // gather raw sigmoid scores
        }
        float s = 1e-20f;
        for (int k = 0; k < 8; k++) s += tw[k];
        float inv = 2.5f / s;    // norm + routed_scaling_factor
        for (int k = 0; k < 8; k++) {
            int e = tki[k];
            int pos = atomicAdd(&g_cnt[e], 1);
            g_tok[e * T + pos] = t;
            g_wt [e * T + pos] = tw[k] * inv;
        }
    }
}

// ============================================================================
// Tiled fp32 GEMMs: BM=BN=64, BK=16, 256 threads, 4x4 microtile.
// A is [M,K] row-major (possibly row-gathered), B is [N,K] row-major (A @ B^T).
// ============================================================================

// ---- routed gate+up (fused) + silu: inter[slot, i] ----
__global__ void __launch_bounds__(256) expert_gu_kernel(
    const float* __restrict__ h,
    const float* __restrict__ w_gate,
    const float* __restrict__ w_up)
{
    int e = blockIdx.z;
    int cnt = g_cnt[e];
    int m0 = blockIdx.y * 64;
    if (m0 >= cnt) return;
    int n0 = blockIdx.x * 64;
    const float* Bg = w_gate + (size_t)e * ID * HD;
    const float* Bu = w_up   + (size_t)e * ID * HD;

    __shared__ float As [16][64];
    __shared__ float Bgs[16][64];
    __shared__ float Bus[16][64];
    __shared__ int rowt[64];

    int tid = threadIdx.x;
    if (tid < 64) {
        int m = m0 + tid;
        rowt[tid] = (m < cnt) ? g_tok[e * T + m] : -1;
    }
    __syncthreads();

    int ar = tid >> 2;
    int ak = (tid & 3) * 4;
    int tx = tid & 15;
    int ty = tid >> 4;

    const float* Arow  = (rowt[ar] >= 0) ? (h + (size_t)rowt[ar] * HD + ak) : 0;
    const float* Bgrow = Bg + (size_t)(n0 + ar) * HD + ak;
    const float* Burow = Bu + (size_t)(n0 + ar) * HD + ak;

    float cg[4][4] = {}, cu[4][4] = {};

    for (int k0 = 0; k0 < HD; k0 += 16) {
        float4 va = Arow ? *(const float4*)(Arow + k0) : make_float4(0.f, 0.f, 0.f, 0.f);
        float4 vg = *(const float4*)(Bgrow + k0);
        float4 vu = *(const float4*)(Burow + k0);
        __syncthreads();
        As [ak + 0][ar] = va.x; As [ak + 1][ar] = va.y; As [ak + 2][ar] = va.z; As [ak + 3][ar] = va.w;
        Bgs[ak + 0][ar] = vg.x; Bgs[ak + 1][ar] = vg.y; Bgs[ak + 2][ar] = vg.z; Bgs[ak + 3][ar] = vg.w;
        Bus[ak + 0][ar] = vu.x; Bus[ak + 1][ar] = vu.y; Bus[ak + 2][ar] = vu.z; Bus[ak + 3][ar] = vu.w;
        __syncthreads();
#pragma unroll
        for (int k = 0; k < 16; k++) {
            float4 a  = *(const float4*)&As [k][ty * 4];
            float4 bg = *(const float4*)&Bgs[k][tx * 4];
            float4 bu = *(const float4*)&Bus[k][tx * 4];
            float av[4]  = {a.x, a.y, a.z, a.w};
            float bgv[4] = {bg.x, bg.y, bg.z, bg.w};
            float buv[4] = {bu.x, bu.y, bu.z, bu.w};
#pragma unroll
            for (int i = 0; i < 4; i++)
#pragma unroll
                for (int j = 0; j < 4; j++) {
                    cg[i][j] += av[i] * bgv[j];
                    cu[i][j] += av[i] * buv[j];
                }
        }
    }

#pragma unroll
    for (int i = 0; i < 4; i++) {
        int m = m0 + ty * 4 + i;
        if (m < cnt) {
            size_t base = ((size_t)e * T + m) * ID + n0 + tx * 4;
#pragma unroll
            for (int j = 0; j < 4; j++) {
                float g = cg[i][j];
                g_inter[base + j] = g / (1.f + expf(-g)) * cu[i][j];
            }
        }
    }
}

// ---- routed down-proj, scaled by routing weight, atomicAdd into out ----
__global__ void __launch_bounds__(256) expert_down_kernel(
    const float* __restrict__ w_down, float* __restrict__ out)
{
    int e = blockIdx.z;
    int cnt = g_cnt[e];
    int m0 = blockIdx.y * 64;
    if (m0 >= cnt) return;
    int n0 = blockIdx.x * 64;
    const float* B = w_down + (size_t)e * HD * ID;

    __shared__ float As[16][64];
    __shared__ float Bs[16][64];
    __shared__ int   s_tok[64];
    __shared__ float s_w[64];

    int tid = threadIdx.x;
    if (tid < 64) {
        int m = m0 + tid;
        s_tok[tid] = (m < cnt) ? g_tok[e * T + m] : 0;
        s_w  [tid] = (m < cnt) ? g_wt [e * T + m] : 0.f;
    }
    __syncthreads();

    int ar = tid >> 2;
    int ak = (tid & 3) * 4;
    int tx = tid & 15;
    int ty = tid >> 4;

    const float* Arow = g_inter + ((size_t)e * T + m0 + ar) * ID + ak;
    const float* Brow = B + (size_t)(n0 + ar) * ID + ak;

    float c[4][4] = {};
    for (int k0 = 0; k0 < ID; k0 += 16) {
        float4 va = *(const float4*)(Arow + k0);
        float4 vb = *(const float4*)(Brow + k0);
        __syncthreads();
        As[ak + 0][ar] = va.x; As[ak + 1][ar] = va.y; As[ak + 2][ar] = va.z; As[ak + 3][ar] = va.w;
        Bs[ak + 0][ar] = vb.x; Bs[ak + 1][ar] = vb.y; Bs[ak + 2][ar] = vb.z; Bs[ak + 3][ar] = vb.w;
        __syncthreads();
#pragma unroll
        for (int k = 0; k < 16; k++) {
            float4 a = *(const float4*)&As[k][ty * 4];
            float4 b = *(const float4*)&Bs[k][tx * 4];
            float av[4] = {a.x, a.y, a.z, a.w};
            float bv[4] = {b.x, b.y, b.z, b.w};
#pragma unroll
            for (int i = 0; i < 4; i++)
#pragma unroll
                for (int j = 0; j < 4; j++)
                    c[i][j] += av[i] * bv[j];
        }
    }

#pragma unroll
    for (int i = 0; i < 4; i++) {
        int m = m0 + ty * 4 + i;
        if (m < cnt) {
            int t = s_tok[ty * 4 + i];
            float wv = s_w[ty * 4 + i];
            float* op = out + (size_t)t * HD + n0 + tx * 4;
#pragma unroll
            for (int j = 0; j < 4; j++)
                atomicAdd(&op[j], c[i][j] * wv);
        }
    }
}

// ---- shared expert gate+up (fused) + silu -> g_inter_sh ----
__global__ void __launch_bounds__(256) shared_gu_kernel(
    const float* __restrict__ h,
    const float* __restrict__ sh_gate,
    const float* __restrict__ sh_up)
{
    int m0 = blockIdx.y * 64;
    int n0 = blockIdx.x * 64;

    __shared__ float As [16][64];
    __shared__ float Bgs[16][64];
    __shared__ float Bus[16][64];

    int tid = threadIdx.x;
    int ar = tid >> 2;
    int ak = (tid & 3) * 4;
    int tx = tid & 15;
    int ty = tid >> 4;

    const float* Arow  = h + (size_t)(m0 + ar) * HD + ak;
    const float* Bgrow = sh_gate + (size_t)(n0 + ar) * HD + ak;
    const float* Burow = sh_up   + (size_t)(n0 + ar) * HD + ak;

    float cg[4][4] = {}, cu[4][4] = {};
    for (int k0 = 0; k0 < HD; k0 += 16) {
        float4 va = *(const float4*)(Arow + k0);
        float4 vg = *(const float4*)(Bgrow + k0);
        float4 vu = *(const float4*)(Burow + k0);
        __syncthreads();
        As [ak + 0][ar] = va.x; As [ak + 1][ar] = va.y; As [ak + 2][ar] = va.z; As [ak + 3][ar] = va.w;
        Bgs[ak + 0][ar] = vg.x; Bgs[ak + 1][ar] = vg.y; Bgs[ak + 2][ar] = vg.z; Bgs[ak + 3][ar] = vg.w;
        Bus[ak + 0][ar] = vu.x; Bus[ak + 1][ar] = vu.y; Bus[ak + 2][ar] = vu.z; Bus[ak + 3][ar] = vu.w;
        __syncthreads();
#pragma unroll
        for (int k = 0; k < 16; k++) {
            float4 a  = *(const float4*)&As [k][ty * 4];
            float4 bg = *(const float4*)&Bgs[k][tx * 4];
            float4 bu = *(const float4*)&Bus[k][tx * 4];
            float av[4]  = {a.x, a.y, a.z, a.w};
            float bgv[4] = {bg.x, bg.y, bg.z, bg.w};
            float buv[4] = {bu.x, bu.y, bu.z, bu.w};
#pragma unroll
            for (int i = 0; i < 4; i++)
#pragma unroll
                for (int j = 0; j < 4; j++) {
                    cg[i][j] += av[i] * bgv[j];
                    cu[i][j] += av[i] * buv[j];
                }
        }
    }
#pragma unroll
    for (int i = 0; i < 4; i++) {
        int m = m0 + ty * 4 + i;
        size_t base = (size_t)m * HD + n0 + tx * 4;
#pragma unroll
        for (int j = 0; j < 4; j++) {
            float g = cg[i][j];
            g_inter_sh[base + j] = g / (1.f + expf(-g)) * cu[i][j];
        }
    }
}

// ---- shared expert down-proj: WRITES out (covers poison) ----
__global__ void __launch_bounds__(256) shared_down_kernel(
    const float* __restrict__ sh_down, float* __restrict__ out)
{
    int m0 = blockIdx.y * 64;
    int n0 = blockIdx.x * 64;

    __shared__ float As[16][64];
    __shared__ float Bs[16][64];

    int tid = threadIdx.x;
    int ar = tid >> 2;
    int ak = (tid & 3) * 4;
    int tx = tid & 15;
    int ty = tid >> 4;

    const float* Arow = g_inter_sh + (size_t)(m0 + ar) * HD + ak;
    const float* Brow = sh_down + (size_t)(n0 + ar) * HD + ak;

    float c[4][4] = {};
    for (int k0 = 0; k0 < HD; k0 += 16) {
        float4 va = *(const float4*)(Arow + k0);
        float4 vb = *(const float4*)(Brow + k0);
        __syncthreads();
        As[ak + 0][ar] = va.x; As[ak + 1][ar] = va.y; As[ak + 2][ar] = va.z; As[ak + 3][ar] = va.w;
        Bs[ak + 0][ar] = vb.x; Bs[ak + 1][ar] = vb.y; Bs[ak + 2][ar] = vb.z; Bs[ak + 3][ar] = vb.w;
        __syncthreads();
#pragma unroll
        for (int k = 0; k < 16; k++) {
            float4 a = *(const float4*)&As[k][ty * 4];
            float4 b = *(const float4*)&Bs[k][tx * 4];
            float av[4] = {a.x, a.y, a.z, a.w};
            float bv[4] = {b.x, b.y, b.z, b.w};
#pragma unroll
            for (int i = 0; i < 4; i++)
#pragma unroll
                for (int j = 0; j < 4; j++)
                    c[i][j] += av[i] * bv[j];
        }
    }
#pragma unroll
    for (int i = 0; i < 4; i++) {
        int m = m0 + ty * 4 + i;
        size_t base = (size_t)m * HD + n0 + tx * 4;
#pragma unroll
        for (int j = 0; j < 4; j++)
            out[base + j] = c[i][j];
    }
}

// ---------------- launch ----------------
extern "C" void kernel_launch(void* const* d_in, const int* in_sizes, int n_in,
                              void* d_out, int out_size) {
    const float* h       = (const float*)d_in[0];
    const float* gate_w  = (const float*)d_in[1];
    const float* gate_b  = (const float*)d_in[2];
    const float* w_gate  = (const float*)d_in[3];
    const float* w_up    = (const float*)d_in[4];
    const float* w_down  = (const float*)d_in[5];
    const float* sh_gate = (const float*)d_in[6];
    const float* sh_up   = (const float*)d_in[7];
    const float* sh_down = (const float*)d_in[8];
    float* out = (float*)d_out;

    zero_kernel<<<1, 32>>>();
    router_kernel<<<T / 4, 128>>>(h, gate_w, gate_b);
    // routed gate+up (per-expert grouped GEMM, early-exit empty tiles)
    expert_gu_kernel<<<dim3(ID / 64, T / 64, NE), 256>>>(h, w_gate, w_up);
    // shared expert
    shared_gu_kernel<<<dim3(HD / 64, T / 64), 256>>>(h, sh_gate, sh_up);
    shared_down_kernel<<<dim3(HD / 64, T / 64), 256>>>(sh_down, out);   // writes out
    // routed down-proj accumulates on top
    expert_down_kernel<<<dim3(HD / 64, T / 64, NE), 256>>>(w_down, out);
}

// round 4
// speedup vs baseline: 2.4529x; 2.4529x over previous
#include <cuda_runtime.h>
#include <cstdint>
#include <math.h>

#define T  2048
#define HD 1024
#define ID 512
#define NE 32

// ---------------- scratch (device globals: allocation-free) ----------------
__device__ int   g_cnt[NE];
__device__ int   g_tok[NE * T];
__device__ float g_wt [NE * T];
__device__ float g_inter   [(size_t)NE * T * ID];
__device__ float g_inter_sh[(size_t)T * HD];

// ---------------- helpers ----------------
__device__ __forceinline__ uint32_t to_tf32(float f) {
    uint32_t r;
    asm("cvt.rna.tf32.f32 %0, %1;" : "=r"(r) : "f"(f));
    return r;
}
__device__ __forceinline__ uint4 to_tf32x4(float4 v) {
    uint4 r;
    r.x = to_tf32(v.x); r.y = to_tf32(v.y); r.z = to_tf32(v.z); r.w = to_tf32(v.w);
    return r;
}
__device__ __forceinline__ void mma_tf32(float* c, const uint32_t* a, const uint32_t* b) {
    asm volatile(
        "mma.sync.aligned.m16n8k8.row.col.f32.tf32.tf32.f32 "
        "{%0,%1,%2,%3}, {%4,%5,%6,%7}, {%8,%9}, {%0,%1,%2,%3};"
        : "+f"(c[0]), "+f"(c[1]), "+f"(c[2]), "+f"(c[3])
        : "r"(a[0]), "r"(a[1]), "r"(a[2]), "r"(a[3]), "r"(b[0]), "r"(b[1]));
}
__device__ __forceinline__ float silu(float g) {
    return g / (1.f + __expf(-g));
}

// ---------------- zero counters ----------------
__global__ void zero_kernel() {
    if (threadIdx.x < NE) g_cnt[threadIdx.x] = 0;
}

// ---------------- router: 1 warp per token ----------------
__global__ void router_kernel(const float* __restrict__ h,
                              const float* __restrict__ gw,
                              const float* __restrict__ gb) {
    __shared__ float s_sc[4][32];
    __shared__ float s_ss[4][32];
    int wid  = threadIdx.x >> 5;
    int lane = threadIdx.x & 31;
    int t = blockIdx.x * 4 + wid;
    if (t >= T) return;

    const float4* hv = (const float4*)(h + (size_t)t * HD);
    const float4* wv = (const float4*)(gw + (size_t)lane * HD);
    float acc = 0.f;
#pragma unroll 8
    for (int j = 0; j < HD / 4; j++) {
        float4 a = hv[j]; float4 b = wv[j];
        acc += a.x * b.x + a.y * b.y + a.z * b.z + a.w * b.w;
    }
    float score = 1.f / (1.f + expf(-acc));
    s_ss[wid][lane] = score;
    s_sc[wid][lane] = score + gb[lane];
    __syncwarp();

    if (lane == 0) {
        float* SC = s_sc[wid];
        float* SS = s_ss[wid];
        float gs[8];
#pragma unroll
        for (int g = 0; g < 8; g++) {
            float m1 = -1e30f, m2 = -1e30f;
#pragma unroll
            for (int q = 0; q < 4; q++) {
                float v = SC[g * 4 + q];
                if (v > m1) { m2 = m1; m1 = v; }
                else if (v > m2) m2 = v;
            }
            gs[g] = m1 + m2;
        }
        unsigned gsel = 0;
        for (int it = 0; it < 4; it++) {
            float best = -1e30f; int bi = 0;
            for (int g = 0; g < 8; g++)
                if (!((gsel >> g) & 1) && gs[g] > best) { best = gs[g]; bi = g; }
            gsel |= 1u << bi;
        }
        float masked[32];
#pragma unroll
        for (int e = 0; e < 32; e++)
            masked[e] = ((gsel >> (e >> 2)) & 1) ? SC[e] : 0.f;
        int tki[8]; float tw[8];
        unsigned used = 0;
        for (int k = 0; k < 8; k++) {
            float best = -1e30f; int bi = 0;
            for (int e = 0; e < 32; e++)
                if (!((used >> e) & 1) && masked[e] > best) { best = masked[e]; bi = e; }
            used |= 1u << bi;
            tki[k] = bi;
            tw[k] = SS[bi];
        }
        float s = 1e-20f;
        for (int k = 0; k < 8; k++) s += tw[k];
        float inv = 2.5f / s;
        for (int k = 0; k < 8; k++) {
            int e = tki[k];
            int pos = atomicAdd(&g_cnt[e], 1);
            g_tok[e * T + pos] = t;
            g_wt [e * T + pos] = tw[k] * inv;
        }
    }
}

// ============================================================================
// GEMM tiles: BM=128, BN=64, BK=32, 256 threads = 8 warps.
// Warp grid 4(m) x 2(n), warp tile 32x32 = 2 m-atoms x 4 n-atoms of m16n8k8.
// Smem row stride 36 floats -> conflict-free fragment loads.
// Software-pipelined: next k-tile LDGs issue before current tile's MMA.
// ============================================================================
#define ASTR 36

// ---- gate+up (fused) + silu ----
template<int ROUTED>
__global__ void __launch_bounds__(256)
gu_mma(const float* __restrict__ h,
       const float* __restrict__ Wg,
       const float* __restrict__ Wu)
{
    constexpr int KD = HD;                     // 1024
    constexpr int NT = KD / 32;
    int e   = ROUTED ? blockIdx.z : 0;
    int cnt = ROUTED ? g_cnt[e] : T;
    int m0  = blockIdx.y * 128;
    if (m0 >= cnt) return;
    int n0  = blockIdx.x * 64;

    __shared__ uint32_t As[128 * ASTR];
    __shared__ uint32_t Bgs[64 * ASTR];
    __shared__ uint32_t Bus[64 * ASTR];
    __shared__ int s_tok[128];

    int tid  = threadIdx.x;
    int wid  = tid >> 5;
    int lane = tid & 31;
    int wm   = wid & 3;        // 0..3  (m block of 32)
    int wn   = wid >> 2;       // 0..1  (n block of 32)

    if (ROUTED && tid < 128) {
        int m = m0 + tid;
        s_tok[tid] = (m < cnt) ? g_tok[e * T + m] : g_tok[e * T];
    }
    __syncthreads();

    const float* Bg0 = Wg + (ROUTED ? (size_t)e * ID * HD : 0) + (size_t)n0 * KD;
    const float* Bu0 = Wu + (ROUTED ? (size_t)e * ID * HD : 0) + (size_t)n0 * KD;

    // A tile load map: 2 threads/row, 4 float4 each
    int a_row = tid >> 1;
    int a_c4  = (tid & 1) * 4;
    const float* a_src;
    if (ROUTED) a_src = h + (size_t)s_tok[a_row] * HD;
    else        a_src = h + (size_t)(m0 + a_row) * HD;
    // B tile load map: 4 threads/row, 2 float4 each
    int b_row = tid >> 2;
    int b_c4  = (tid & 3) * 2;
    const float* bg_src = Bg0 + (size_t)b_row * KD;
    const float* bu_src = Bu0 + (size_t)b_row * KD;

    float cg[2][4][4] = {}, cu[2][4][4] = {};

    float4 av[4], gv[2], uv[2];
    // prologue: load k-tile 0
#pragma unroll
    for (int j = 0; j < 4; j++) av[j] = ((const float4*)a_src)[a_c4 + j];
#pragma unroll
    for (int j = 0; j < 2; j++) {
        gv[j] = ((const float4*)bg_src)[b_c4 + j];
        uv[j] = ((const float4*)bu_src)[b_c4 + j];
    }

    for (int kt = 0; kt < NT; kt++) {
        __syncthreads();
#pragma unroll
        for (int j = 0; j < 4; j++)
            *(uint4*)&As[a_row * ASTR + (a_c4 + j) * 4] = to_tf32x4(av[j]);
#pragma unroll
        for (int j = 0; j < 2; j++) {
            *(uint4*)&Bgs[b_row * ASTR + (b_c4 + j) * 4] = to_tf32x4(gv[j]);
            *(uint4*)&Bus[b_row * ASTR + (b_c4 + j) * 4] = to_tf32x4(uv[j]);
        }
        __syncthreads();

        // prefetch next k-tile (overlaps with MMA below)
        if (kt + 1 < NT) {
            int k1 = (kt + 1) * 32;
#pragma unroll
            for (int j = 0; j < 4; j++) av[j] = ((const float4*)(a_src + k1))[a_c4 + j];
#pragma unroll
            for (int j = 0; j < 2; j++) {
                gv[j] = ((const float4*)(bg_src + k1))[b_c4 + j];
                uv[j] = ((const float4*)(bu_src + k1))[b_c4 + j];
            }
        }

#pragma unroll
        for (int ks = 0; ks < 4; ks++) {
            int kk = ks * 8 + (lane & 3);
            uint32_t af[2][4];
#pragma unroll
            for (int mi = 0; mi < 2; mi++) {
                int r = wm * 32 + mi * 16 + (lane >> 2);
                af[mi][0] = As[r * ASTR + kk];
                af[mi][1] = As[(r + 8) * ASTR + kk];
                af[mi][2] = As[r * ASTR + kk + 4];
                af[mi][3] = As[(r + 8) * ASTR + kk + 4];
            }
            uint32_t bgf[4][2], buf[4][2];
#pragma unroll
            for (int ni = 0; ni < 4; ni++) {
                int n = wn * 32 + ni * 8 + (lane >> 2);
                bgf[ni][0] = Bgs[n * ASTR + kk];
                bgf[ni][1] = Bgs[n * ASTR + kk + 4];
                buf[ni][0] = Bus[n * ASTR + kk];
                buf[ni][1] = Bus[n * ASTR + kk + 4];
            }
#pragma unroll
            for (int mi = 0; mi < 2; mi++)
#pragma unroll
                for (int ni = 0; ni < 4; ni++) {
                    mma_tf32(cg[mi][ni], af[mi], bgf[ni]);
                    mma_tf32(cu[mi][ni], af[mi], buf[ni]);
                }
        }
    }

    // epilogue: silu(g)*u
    int gr = lane >> 2;
    int gc = (lane & 3) * 2;
    constexpr int OD = ROUTED ? ID : HD;
    float* obase;
    if (ROUTED) obase = g_inter + ((size_t)e * T + m0) * OD;
    else        obase = g_inter_sh + (size_t)m0 * OD;

#pragma unroll
    for (int mi = 0; mi < 2; mi++) {
        int mA = wm * 32 + mi * 16 + gr;
        int mB = mA + 8;
        bool vA = (m0 + mA) < cnt;
        bool vB = (m0 + mB) < cnt;
#pragma unroll
        for (int ni = 0; ni < 4; ni++) {
            int n = n0 + wn * 32 + ni * 8 + gc;
            float* c = cg[mi][ni];
            float* d = cu[mi][ni];
            if (vA) {
                float2 o = make_float2(silu(c[0]) * d[0], silu(c[1]) * d[1]);
                *(float2*)(obase + (size_t)mA * OD + n) = o;
            }
            if (vB) {
                float2 o = make_float2(silu(c[2]) * d[2], silu(c[3]) * d[3]);
                *(float2*)(obase + (size_t)mB * OD + n) = o;
            }
        }
    }
}

// ---- down-proj ----
template<int ROUTED>
__global__ void __launch_bounds__(256)
down_mma(const float* __restrict__ Wd, float* __restrict__ out)
{
    constexpr int KD = ROUTED ? ID : HD;
    constexpr int NT = KD / 32;
    int e   = ROUTED ? blockIdx.z : 0;
    int cnt = ROUTED ? g_cnt[e] : T;
    int m0  = blockIdx.y * 128;
    if (m0 >= cnt) return;
    int n0  = blockIdx.x * 64;

    __shared__ uint32_t As[128 * ASTR];
    __shared__ uint32_t Bs[64 * ASTR];
    __shared__ int   s_tok[128];
    __shared__ float s_w[128];

    int tid  = threadIdx.x;
    int wid  = tid >> 5;
    int lane = tid & 31;
    int wm   = wid & 3;
    int wn   = wid >> 2;

    if (ROUTED && tid < 128) {
        int m = m0 + tid;
        s_tok[tid] = (m < cnt) ? g_tok[e * T + m] : 0;
        s_w[tid]   = (m < cnt) ? g_wt [e * T + m] : 0.f;
    }
    __syncthreads();

    const float* A0 = ROUTED ? (g_inter + ((size_t)e * T + m0) * KD)
                             : (g_inter_sh + (size_t)m0 * KD);
    const float* B0 = Wd + (ROUTED ? (size_t)e * HD * ID : 0) + (size_t)n0 * KD;

    int a_row = tid >> 1;
    int a_c4  = (tid & 1) * 4;
    const float* a_src = A0 + (size_t)a_row * KD;
    int b_row = tid >> 2;
    int b_c4  = (tid & 3) * 2;
    const float* b_src = B0 + (size_t)b_row * KD;

    float cc[2][4][4] = {};

    float4 av[4], bv[2];
#pragma unroll
    for (int j = 0; j < 4; j++) av[j] = ((const float4*)a_src)[a_c4 + j];
#pragma unroll
    for (int j = 0; j < 2; j++) bv[j] = ((const float4*)b_src)[b_c4 + j];

    for (int kt = 0; kt < NT; kt++) {
        __syncthreads();
#pragma unroll
        for (int j = 0; j < 4; j++)
            *(uint4*)&As[a_row * ASTR + (a_c4 + j) * 4] = to_tf32x4(av[j]);
#pragma unroll
        for (int j = 0; j < 2; j++)
            *(uint4*)&Bs[b_row * ASTR + (b_c4 + j) * 4] = to_tf32x4(bv[j]);
        __syncthreads();

        if (kt + 1 < NT) {
            int k1 = (kt + 1) * 32;
#pragma unroll
            for (int j = 0; j < 4; j++) av[j] = ((const float4*)(a_src + k1))[a_c4 + j];
#pragma unroll
            for (int j = 0; j < 2; j++) bv[j] = ((const float4*)(b_src + k1))[b_c4 + j];
        }

#pragma unroll
        for (int ks = 0; ks < 4; ks++) {
            int kk = ks * 8 + (lane & 3);
            uint32_t af[2][4];
#pragma unroll
            for (int mi = 0; mi < 2; mi++) {
                int r = wm * 32 + mi * 16 + (lane >> 2);
                af[mi][0] = As[r * ASTR + kk];
                af[mi][1] = As[(r + 8) * ASTR + kk];
                af[mi][2] = As[r * ASTR + kk + 4];
                af[mi][3] = As[(r + 8) * ASTR + kk + 4];
            }
            uint32_t bf[4][2];
#pragma unroll
            for (int ni = 0; ni < 4; ni++) {
                int n = wn * 32 + ni * 8 + (lane >> 2);
                bf[ni][0] = Bs[n * ASTR + kk];
                bf[ni][1] = Bs[n * ASTR + kk + 4];
            }
#pragma unroll
            for (int mi = 0; mi < 2; mi++)
#pragma unroll
                for (int ni = 0; ni < 4; ni++)
                    mma_tf32(cc[mi][ni], af[mi], bf[ni]);
        }
    }

    int gr = lane >> 2;
    int gc = (lane & 3) * 2;

#pragma unroll
    for (int mi = 0; mi < 2; mi++) {
        int mA = wm * 32 + mi * 16 + gr;
        int mB = mA + 8;
        bool vA = (m0 + mA) < cnt;
        bool vB = (m0 + mB) < cnt;
#pragma unroll
        for (int ni = 0; ni < 4; ni++) {
            int n = n0 + wn * 32 + ni * 8 + gc;
            float* c = cc[mi][ni];
            if (ROUTED) {
                if (vA) {
                    float w = s_w[mA];
                    float* p = out + (size_t)s_tok[mA] * HD + n;
                    atomicAdd(p,     c[0] * w);
                    atomicAdd(p + 1, c[1] * w);
                }
                if (vB) {
                    float w = s_w[mB];
                    float* p = out + (size_t)s_tok[mB] * HD + n;
                    atomicAdd(p,     c[2] * w);
                    atomicAdd(p + 1, c[3] * w);
                }
            } else {
                *(float2*)(out + (size_t)(m0 + mA) * HD + n) = make_float2(c[0], c[1]);
                *(float2*)(out + (size_t)(m0 + mB) * HD + n) = make_float2(c[2], c[3]);
            }
        }
    }
}

// ---------------- launch ----------------
extern "C" void kernel_launch(void* const* d_in, const int* in_sizes, int n_in,
                              void* d_out, int out_size) {
    const float* h       = (const float*)d_in[0];
    const float* gate_w  = (const float*)d_in[1];
    const float* gate_b  = (const float*)d_in[2];
    const float* w_gate  = (const float*)d_in[3];
    const float* w_up    = (const float*)d_in[4];
    const float* w_down  = (const float*)d_in[5];
    const float* sh_gate = (const float*)d_in[6];
    const float* sh_up   = (const float*)d_in[7];
    const float* sh_down = (const float*)d_in[8];
    float* out = (float*)d_out;

    zero_kernel<<<1, 32>>>();
    router_kernel<<<T / 4, 128>>>(h, gate_w, gate_b);

    // routed gate+up: N=512 -> 8 n-tiles, M tiles over cnt (early exit)
    gu_mma<1><<<dim3(ID / 64, T / 128, NE), 256>>>(h, w_gate, w_up);
    // shared gate+up: N=1024 -> 16 n-tiles
    gu_mma<0><<<dim3((2 * ID) / 64, T / 128, 1), 256>>>(h, sh_gate, sh_up);
    // shared down-proj writes out (covers poison)
    down_mma<0><<<dim3(HD / 64, T / 128, 1), 256>>>(sh_down, out);
    // routed down-proj accumulates
    down_mma<1><<<dim3(HD / 64, T / 128, NE), 256>>>(w_down, out);
}

// round 5
// speedup vs baseline: 2.5303x; 1.0316x over previous
#include <cuda_runtime.h>
#include <cstdint>
#include <math.h>

#define T  2048
#define HD 1024
#define ID 512
#define NE 32

// ---------------- scratch (device globals: allocation-free) ----------------
__device__ int   g_cnt[NE];
__device__ int   g_tok[NE * T];
__device__ float g_wt [NE * T];
__device__ float g_inter   [(size_t)NE * T * ID];
__device__ float g_inter_sh[(size_t)T * HD];

// ---------------- helpers ----------------
__device__ __forceinline__ uint32_t smem_u32(const void* p) {
    uint32_t a;
    asm("{ .reg .u64 t; cvta.to.shared.u64 t, %1; cvt.u32.u64 %0, t; }" : "=r"(a) : "l"(p));
    return a;
}
// LDS + convert to tf32 (rna) at fragment-load time
__device__ __forceinline__ uint32_t ldcvt(const float* p) {
    uint32_t r;
    asm("cvt.rna.tf32.f32 %0, %1;" : "=r"(r) : "f"(*p));
    return r;
}
__device__ __forceinline__ void mma_tf32(float* c, const uint32_t* a, const uint32_t* b) {
    asm volatile(
        "mma.sync.aligned.m16n8k8.row.col.f32.tf32.tf32.f32 "
        "{%0,%1,%2,%3}, {%4,%5,%6,%7}, {%8,%9}, {%0,%1,%2,%3};"
        : "+f"(c[0]), "+f"(c[1]), "+f"(c[2]), "+f"(c[3])
        : "r"(a[0]), "r"(a[1]), "r"(a[2]), "r"(a[3]), "r"(b[0]), "r"(b[1]));
}
__device__ __forceinline__ float silu(float g) {
    return g / (1.f + __expf(-g));
}
#define CP16(dst, src) asm volatile("cp.async.cg.shared.global [%0], [%1], 16;" :: "r"(dst), "l"(src))
#define CP_COMMIT()    asm volatile("cp.async.commit_group;" ::: "memory")
#define CP_WAIT(n)     asm volatile("cp.async.wait_group %0;" :: "n"(n) : "memory")

// ---------------- zero counters ----------------
__global__ void zero_kernel() {
    if (threadIdx.x < NE) g_cnt[threadIdx.x] = 0;
}

// ---------------- router: 1 warp per token ----------------
__global__ void router_kernel(const float* __restrict__ h,
                              const float* __restrict__ gw,
                              const float* __restrict__ gb) {
    __shared__ float s_sc[4][32];
    __shared__ float s_ss[4][32];
    int wid  = threadIdx.x >> 5;
    int lane = threadIdx.x & 31;
    int t = blockIdx.x * 4 + wid;
    if (t >= T) return;

    const float4* hv = (const float4*)(h + (size_t)t * HD);
    const float4* wv = (const float4*)(gw + (size_t)lane * HD);
    float acc = 0.f;
#pragma unroll 8
    for (int j = 0; j < HD / 4; j++) {
        float4 a = hv[j]; float4 b = wv[j];
        acc += a.x * b.x + a.y * b.y + a.z * b.z + a.w * b.w;
    }
    float score = 1.f / (1.f + expf(-acc));
    s_ss[wid][lane] = score;
    s_sc[wid][lane] = score + gb[lane];
    __syncwarp();

    if (lane == 0) {
        float* SC = s_sc[wid];
        float* SS = s_ss[wid];
        float gs[8];
#pragma unroll
        for (int g = 0; g < 8; g++) {
            float m1 = -1e30f, m2 = -1e30f;
#pragma unroll
            for (int q = 0; q < 4; q++) {
                float v = SC[g * 4 + q];
                if (v > m1) { m2 = m1; m1 = v; }
                else if (v > m2) m2 = v;
            }
            gs[g] = m1 + m2;
        }
        unsigned gsel = 0;
        for (int it = 0; it < 4; it++) {
            float best = -1e30f; int bi = 0;
            for (int g = 0; g < 8; g++)
                if (!((gsel >> g) & 1) && gs[g] > best) { best = gs[g]; bi = g; }
            gsel |= 1u << bi;
        }
        float masked[32];
#pragma unroll
        for (int e = 0; e < 32; e++)
            masked[e] = ((gsel >> (e >> 2)) & 1) ? SC[e] : 0.f;
        int tki[8]; float tw[8];
        unsigned used = 0;
        for (int k = 0; k < 8; k++) {
            float best = -1e30f; int bi = 0;
            for (int e = 0; e < 32; e++)
                if (!((used >> e) & 1) && masked[e] > best) { best = masked[e]; bi = e; }
            used |= 1u << bi;
            tki[k] = bi;
            tw[k] = SS[bi];
        }
        float s = 1e-20f;
        for (int k = 0; k < 8; k++) s += tw[k];
        float inv = 2.5f / s;
        for (int k = 0; k < 8; k++) {
            int e = tki[k];
            int pos = atomicAdd(&g_cnt[e], 1);
            g_tok[e * T + pos] = t;
            g_wt [e * T + pos] = tw[k] * inv;
        }
    }
}

// ============================================================================
// GEMM tiles: BM=128, BN=64, BK=32, 256 threads = 8 warps, 2 blocks/SM.
// Warp grid 4(m) x 2(n), warp tile 32x32 = 2 m-atoms x 4 n-atoms of m16n8k8.
// cp.async double-buffered smem (raw fp32), cvt->tf32 at fragment load.
// Smem word stride 36 -> conflict-free fragment loads.
// ============================================================================
#define ASTR 36
// gu stage: A 128*36 + Bg 64*36 + Bu 64*36 = 9216 words = 36864 B
#define GU_STAGE_W   9216
#define GU_SMEM      (2 * GU_STAGE_W * 4)
// down stage: A 128*36 + B 64*36 = 6912 words = 27648 B
#define DN_STAGE_W   6912
#define DN_SMEM      (2 * DN_STAGE_W * 4)

// ---- gate+up (fused) + silu ----
template<int ROUTED>
__global__ void __launch_bounds__(256, 2)
gu_mma(const float* __restrict__ h,
       const float* __restrict__ Wg,
       const float* __restrict__ Wu)
{
    constexpr int KD = HD;
    constexpr int NT = KD / 32;
    int e   = ROUTED ? blockIdx.z : 0;
    int cnt = ROUTED ? g_cnt[e] : T;
    int m0  = blockIdx.y * 128;
    if (m0 >= cnt) return;
    int n0  = blockIdx.x * 64;

    extern __shared__ float smem[];
    uint32_t smem_b = smem_u32(smem);
    __shared__ int s_tok[128];

    int tid  = threadIdx.x;
    int wid  = tid >> 5;
    int lane = tid & 31;
    int wm   = wid & 3;
    int wn   = wid >> 2;

    if (ROUTED && tid < 128) {
        int m = m0 + tid;
        s_tok[tid] = (m < cnt) ? g_tok[e * T + m] : g_tok[e * T];
    }
    __syncthreads();

    const float* Bg0 = Wg + (ROUTED ? (size_t)e * ID * HD : 0) + (size_t)n0 * KD;
    const float* Bu0 = Wu + (ROUTED ? (size_t)e * ID * HD : 0) + (size_t)n0 * KD;

    int a_row = tid >> 1;
    int a_c4  = (tid & 1) * 4;                  // float4 index (0 or 4)
    const float* a_src;
    if (ROUTED) a_src = h + (size_t)s_tok[a_row] * HD;
    else        a_src = h + (size_t)(m0 + a_row) * HD;
    int b_row = tid >> 2;
    int b_c4  = (tid & 3) * 2;                  // float4 index (0,2,4,6)
    const float* bg_src = Bg0 + (size_t)b_row * KD;
    const float* bu_src = Bu0 + (size_t)b_row * KD;

    uint32_t a_dst = smem_b + (uint32_t)a_row * 144u + (uint32_t)a_c4 * 16u;
    uint32_t g_dst = smem_b + 18432u + (uint32_t)b_row * 144u + (uint32_t)b_c4 * 16u;
    uint32_t u_dst = smem_b + 27648u + (uint32_t)b_row * 144u + (uint32_t)b_c4 * 16u;

#define GU_COPY(st, k0) do { \
    uint32_t off = (uint32_t)(st) * (GU_STAGE_W * 4); \
    const float* ap = a_src  + (k0) + a_c4 * 4; \
    const float* gp = bg_src + (k0) + b_c4 * 4; \
    const float* up = bu_src + (k0) + b_c4 * 4; \
    CP16(a_dst + off,      ap);      CP16(a_dst + off + 16, ap + 4); \
    CP16(a_dst + off + 32, ap + 8);  CP16(a_dst + off + 48, ap + 12); \
    CP16(g_dst + off,      gp);      CP16(g_dst + off + 16, gp + 4); \
    CP16(u_dst + off,      up);      CP16(u_dst + off + 16, up + 4); \
} while (0)

    float cg[2][4][4] = {}, cu[2][4][4] = {};

    GU_COPY(0, 0);
    CP_COMMIT();

    for (int kt = 0; kt < NT; kt++) {
        if (kt + 1 < NT) {
            GU_COPY((kt + 1) & 1, (kt + 1) * 32);
            CP_COMMIT();
            CP_WAIT(1);
        } else {
            CP_WAIT(0);
        }
        __syncthreads();

        const float* As = smem + (kt & 1) * GU_STAGE_W;
        const float* Bg = As + 4608;
        const float* Bu = As + 6912;

#pragma unroll
        for (int ks = 0; ks < 4; ks++) {
            int kk = ks * 8 + (lane & 3);
            uint32_t af[2][4];
#pragma unroll
            for (int mi = 0; mi < 2; mi++) {
                int r = wm * 32 + mi * 16 + (lane >> 2);
                af[mi][0] = ldcvt(&As[r * ASTR + kk]);
                af[mi][1] = ldcvt(&As[(r + 8) * ASTR + kk]);
                af[mi][2] = ldcvt(&As[r * ASTR + kk + 4]);
                af[mi][3] = ldcvt(&As[(r + 8) * ASTR + kk + 4]);
            }
            uint32_t bgf[4][2], buf[4][2];
#pragma unroll
            for (int ni = 0; ni < 4; ni++) {
                int n = wn * 32 + ni * 8 + (lane >> 2);
                bgf[ni][0] = ldcvt(&Bg[n * ASTR + kk]);
                bgf[ni][1] = ldcvt(&Bg[n * ASTR + kk + 4]);
                buf[ni][0] = ldcvt(&Bu[n * ASTR + kk]);
                buf[ni][1] = ldcvt(&Bu[n * ASTR + kk + 4]);
            }
#pragma unroll
            for (int mi = 0; mi < 2; mi++)
#pragma unroll
                for (int ni = 0; ni < 4; ni++) {
                    mma_tf32(cg[mi][ni], af[mi], bgf[ni]);
                    mma_tf32(cu[mi][ni], af[mi], buf[ni]);
                }
        }
        __syncthreads();
    }
#undef GU_COPY

    // epilogue: silu(g)*u
    int gr = lane >> 2;
    int gc = (lane & 3) * 2;
    constexpr int OD = ROUTED ? ID : HD;
    float* obase;
    if (ROUTED) obase = g_inter + ((size_t)e * T + m0) * OD;
    else        obase = g_inter_sh + (size_t)m0 * OD;

#pragma unroll
    for (int mi = 0; mi < 2; mi++) {
        int mA = wm * 32 + mi * 16 + gr;
        int mB = mA + 8;
        bool vA = (m0 + mA) < cnt;
        bool vB = (m0 + mB) < cnt;
#pragma unroll
        for (int ni = 0; ni < 4; ni++) {
            int n = n0 + wn * 32 + ni * 8 + gc;
            float* c = cg[mi][ni];
            float* d = cu[mi][ni];
            if (vA) {
                float2 o = make_float2(silu(c[0]) * d[0], silu(c[1]) * d[1]);
                *(float2*)(obase + (size_t)mA * OD + n) = o;
            }
            if (vB) {
                float2 o = make_float2(silu(c[2]) * d[2], silu(c[3]) * d[3]);
                *(float2*)(obase + (size_t)mB * OD + n) = o;
            }
        }
    }
}

// ---- down-proj ----
template<int ROUTED>
__global__ void __launch_bounds__(256, 2)
down_mma(const float* __restrict__ Wd, float* __restrict__ out)
{
    constexpr int KD = ROUTED ? ID : HD;
    constexpr int NT = KD / 32;
    int e   = ROUTED ? blockIdx.z : 0;
    int cnt = ROUTED ? g_cnt[e] : T;
    int m0  = blockIdx.y * 128;
    if (m0 >= cnt) return;
    int n0  = blockIdx.x * 64;

    extern __shared__ float smem[];
    uint32_t smem_b = smem_u32(smem);
    __shared__ int   s_tok[128];
    __shared__ float s_w[128];

    int tid  = threadIdx.x;
    int wid  = tid >> 5;
    int lane = tid & 31;
    int wm   = wid & 3;
    int wn   = wid >> 2;

    if (ROUTED && tid < 128) {
        int m = m0 + tid;
        s_tok[tid] = (m < cnt) ? g_tok[e * T + m] : 0;
        s_w[tid]   = (m < cnt) ? g_wt [e * T + m] : 0.f;
    }
    __syncthreads();

    const float* A0 = ROUTED ? (g_inter + ((size_t)e * T + m0) * KD)
                             : (g_inter_sh + (size_t)m0 * KD);
    const float* B0 = Wd + (ROUTED ? (size_t)e * HD * ID : 0) + (size_t)n0 * KD;

    int a_row = tid >> 1;
    int a_c4  = (tid & 1) * 4;
    const float* a_src = A0 + (size_t)a_row * KD;
    int b_row = tid >> 2;
    int b_c4  = (tid & 3) * 2;
    const float* b_src = B0 + (size_t)b_row * KD;

    uint32_t a_dst = smem_b + (uint32_t)a_row * 144u + (uint32_t)a_c4 * 16u;
    uint32_t b_dst = smem_b + 18432u + (uint32_t)b_row * 144u + (uint32_t)b_c4 * 16u;

#define DN_COPY(st, k0) do { \
    uint32_t off = (uint32_t)(st) * (DN_STAGE_W * 4); \
    const float* ap = a_src + (k0) + a_c4 * 4; \
    const float* bp = b_src + (k0) + b_c4 * 4; \
    CP16(a_dst + off,      ap);      CP16(a_dst + off + 16, ap + 4); \
    CP16(a_dst + off + 32, ap + 8);  CP16(a_dst + off + 48, ap + 12); \
    CP16(b_dst + off,      bp);      CP16(b_dst + off + 16, bp + 4); \
} while (0)

    float cc[2][4][4] = {};

    DN_COPY(0, 0);
    CP_COMMIT();

    for (int kt = 0; kt < NT; kt++) {
        if (kt + 1 < NT) {
            DN_COPY((kt + 1) & 1, (kt + 1) * 32);
            CP_COMMIT();
            CP_WAIT(1);
        } else {
            CP_WAIT(0);
        }
        __syncthreads();

        const float* As = smem + (kt & 1) * DN_STAGE_W;
        const float* Bs = As + 4608;

#pragma unroll
        for (int ks = 0; ks < 4; ks++) {
            int kk = ks * 8 + (lane & 3);
            uint32_t af[2][4];
#pragma unroll
            for (int mi = 0; mi < 2; mi++) {
                int r = wm * 32 + mi * 16 + (lane >> 2);
                af[mi][0] = ldcvt(&As[r * ASTR + kk]);
                af[mi][1] = ldcvt(&As[(r + 8) * ASTR + kk]);
                af[mi][2] = ldcvt(&As[r * ASTR + kk + 4]);
                af[mi][3] = ldcvt(&As[(r + 8) * ASTR + kk + 4]);
            }
            uint32_t bf[4][2];
#pragma unroll
            for (int ni = 0; ni < 4; ni++) {
                int n = wn * 32 + ni * 8 + (lane >> 2);
                bf[ni][0] = ldcvt(&Bs[n * ASTR + kk]);
                bf[ni][1] = ldcvt(&Bs[n * ASTR + kk + 4]);
            }
#pragma unroll
            for (int mi = 0; mi < 2; mi++)
#pragma unroll
                for (int ni = 0; ni < 4; ni++)
                    mma_tf32(cc[mi][ni], af[mi], bf[ni]);
        }
        __syncthreads();
    }
#undef DN_COPY

    int gr = lane >> 2;
    int gc = (lane & 3) * 2;

#pragma unroll
    for (int mi = 0; mi < 2; mi++) {
        int mA = wm * 32 + mi * 16 + gr;
        int mB = mA + 8;
        bool vA = (m0 + mA) < cnt;
        bool vB = (m0 + mB) < cnt;
#pragma unroll
        for (int ni = 0; ni < 4; ni++) {
            int n = n0 + wn * 32 + ni * 8 + gc;
            float* c = cc[mi][ni];
            if (ROUTED) {
                if (vA) {
                    float w = s_w[mA];
                    float* p = out + (size_t)s_tok[mA] * HD + n;
                    atomicAdd(p,     c[0] * w);
                    atomicAdd(p + 1, c[1] * w);
                }
                if (vB) {
                    float w = s_w[mB];
                    float* p = out + (size_t)s_tok[mB] * HD + n;
                    atomicAdd(p,     c[2] * w);
                    atomicAdd(p + 1, c[3] * w);
                }
            } else {
                *(float2*)(out + (size_t)(m0 + mA) * HD + n) = make_float2(c[0], c[1]);
                *(float2*)(out + (size_t)(m0 + mB) * HD + n) = make_float2(c[2], c[3]);
            }
        }
    }
}

// ---------------- launch ----------------
extern "C" void kernel_launch(void* const* d_in, const int* in_sizes, int n_in,
                              void* d_out, int out_size) {
    const float* h       = (const float*)d_in[0];
    const float* gate_w  = (const float*)d_in[1];
    const float* gate_b  = (const float*)d_in[2];
    const float* w_gate  = (const float*)d_in[3];
    const float* w_up    = (const float*)d_in[4];
    const float* w_down  = (const float*)d_in[5];
    const float* sh_gate = (const float*)d_in[6];
    const float* sh_up   = (const float*)d_in[7];
    const float* sh_down = (const float*)d_in[8];
    float* out = (float*)d_out;

    cudaFuncSetAttribute(gu_mma<1>,   cudaFuncAttributeMaxDynamicSharedMemorySize, GU_SMEM);
    cudaFuncSetAttribute(gu_mma<0>,   cudaFuncAttributeMaxDynamicSharedMemorySize, GU_SMEM);
    cudaFuncSetAttribute(down_mma<1>, cudaFuncAttributeMaxDynamicSharedMemorySize, DN_SMEM);
    cudaFuncSetAttribute(down_mma<0>, cudaFuncAttributeMaxDynamicSharedMemorySize, DN_SMEM);

    zero_kernel<<<1, 32>>>();
    router_kernel<<<T / 4, 128>>>(h, gate_w, gate_b);

    // routed gate+up: N=512 -> 8 n-tiles, M tiles over cnt (early exit)
    gu_mma<1><<<dim3(ID / 64, T / 128, NE), 256, GU_SMEM>>>(h, w_gate, w_up);
    // shared gate+up: N=1024 -> 16 n-tiles
    gu_mma<0><<<dim3((2 * ID) / 64, T / 128, 1), 256, GU_SMEM>>>(h, sh_gate, sh_up);
    // shared down-proj writes out (covers poison)
    down_mma<0><<<dim3(HD / 64, T / 128, 1), 256, DN_SMEM>>>(sh_down, out);
    // routed down-proj accumulates
    down_mma<1><<<dim3(HD / 64, T / 128, NE), 256, DN_SMEM>>>(w_down, out);
}